// round 1
// baseline (speedup 1.0000x reference)
#include <cuda_runtime.h>
#include <math.h>

#define NCH 16
#define NB 5
#define MAXN 20000
#define MAXE 640000

// Scratch (allocation-free: __device__ globals)
__device__ int g_counts[MAXN];
__device__ int g_row[MAXN + 1];
__device__ int g_cursor[MAXN];
__device__ int g_eids[MAXE];

__global__ void k_zero(int n) {
    int i = blockIdx.x * blockDim.x + threadIdx.x;
    if (i < n) g_counts[i] = 0;
}

__global__ void k_hist(const int* __restrict__ recv, int E) {
    int i = blockIdx.x * blockDim.x + threadIdx.x;
    if (i < E) atomicAdd(&g_counts[recv[i]], 1);
}

// Single-block exclusive scan over n counters (n ~ 20000).
__global__ void k_scan(int n) {
    __shared__ int sh[1024];
    __shared__ int carry;
    if (threadIdx.x == 0) carry = 0;
    __syncthreads();
    for (int base = 0; base < n; base += 1024) {
        int i = base + threadIdx.x;
        int v = (i < n) ? g_counts[i] : 0;
        sh[threadIdx.x] = v;
        __syncthreads();
        #pragma unroll
        for (int off = 1; off < 1024; off <<= 1) {
            int t = (threadIdx.x >= (unsigned)off) ? sh[threadIdx.x - off] : 0;
            __syncthreads();
            sh[threadIdx.x] += t;
            __syncthreads();
        }
        int excl = sh[threadIdx.x] - v + carry;
        if (i < n) { g_row[i] = excl; g_cursor[i] = excl; }
        __syncthreads();
        if (threadIdx.x == 0) carry += sh[1023];
        __syncthreads();
    }
    if (threadIdx.x == 0) g_row[n] = carry;
}

__global__ void k_scatter(const int* __restrict__ recv, int E) {
    int i = blockIdx.x * blockDim.x + threadIdx.x;
    if (i < E) {
        int pos = atomicAdd(&g_cursor[recv[i]], 1);
        g_eids[pos] = i;
    }
}

// Main gather kernel: one warp per node. lane = (half<<4)|channel.
// Half-warps process 2 edges per iteration; accumulators combined via shfl.
__global__ void __launch_bounds__(256) k_main(
    const float* __restrict__ nodes0, const float* __restrict__ nodes1,
    const float* __restrict__ edges,  const int* __restrict__ senders,
    const float* __restrict__ c00, const float* __restrict__ c01,
    const float* __restrict__ c10, const float* __restrict__ c11,
    const float* __restrict__ w000, const float* __restrict__ w011,
    const float* __restrict__ w101, const float* __restrict__ w110,
    const float* __restrict__ w111,
    float* __restrict__ out0, float* __restrict__ out1, int n_nodes)
{
    int warp = (blockIdx.x * blockDim.x + threadIdx.x) >> 5;
    if (warp >= n_nodes) return;
    int lane = threadIdx.x & 31;
    int c = lane & 15;
    int half = lane >> 4;

    // Per-channel radial coefficients in registers.
    float a00[NB], a01[NB], a10[NB], a11[NB];
    #pragma unroll
    for (int k = 0; k < NB; k++) {
        a00[k] = c00[c * NB + k];
        a01[k] = c01[c * NB + k];
        a10[k] = c10[c * NB + k];
        a11[k] = c11[c * NB + k];
    }
    const float Y00 = 0.28209479177387814f;
    const float Y1C = 0.4886025119029199f;
    // Fold weights with path constants.
    float W000f = w000[c] * Y00;                      // path 000 (times f00 = rad00*Y00)
    float W011  = w011[c];                            // path 011
    float W101f = w101[c] * Y00;                      // path 101 (times f10 = rad10*Y00)
    float W110f = w110[c] * 0.57735026918962576f;     // path 110, 1/sqrt(3)
    float W111f = w111[c] * 0.70710678118654752f;     // path 111, 1/sqrt(2)

    // RBF factorization constants: rbf_k = exp(-0.7 r^2) * t^k * K_k, t = exp(1.225 r)
    float K1 = expf(-0.7f * 0.875f * 0.875f);
    float K2 = expf(-0.7f * 1.75f  * 1.75f);
    float K3 = expf(-0.7f * 2.625f * 2.625f);
    float K4 = expf(-0.7f * 3.5f   * 3.5f);

    int rs = g_row[warp];
    int re = g_row[warp + 1];

    float m0a = 0.f, m0b = 0.f;
    float m1a0 = 0.f, m1a1 = 0.f, m1a2 = 0.f;
    float m1b0 = 0.f, m1b1 = 0.f, m1b2 = 0.f;
    float m1c0 = 0.f, m1c1 = 0.f, m1c2 = 0.f;

    for (int base = rs; base < re; base += 2) {
        int it = base + half;
        bool valid = (it < re);
        int safe = valid ? it : base;          // base < re guaranteed here
        int e = g_eids[safe];
        int s = senders[e];
        float ex = edges[3 * e + 0];
        float ey = edges[3 * e + 1];
        float ez = edges[3 * e + 2];
        float r2 = fmaf(ex, ex, fmaf(ey, ey, ez * ez));
        float r  = sqrtf(r2);
        float E0 = expf(-0.7f * r2);
        float t  = expf(1.225f * r);
        float p1 = E0 * t, p2 = p1 * t, p3 = p2 * t, p4 = p3 * t;
        float rb0 = E0, rb1 = p1 * K1, rb2 = p2 * K2, rb3 = p3 * K3, rb4 = p4 * K4;

        float rad00 = fmaf(rb4, a00[4], fmaf(rb3, a00[3], fmaf(rb2, a00[2], fmaf(rb1, a00[1], rb0 * a00[0]))));
        float rad01 = fmaf(rb4, a01[4], fmaf(rb3, a01[3], fmaf(rb2, a01[2], fmaf(rb1, a01[1], rb0 * a01[0]))));
        float rad10 = fmaf(rb4, a10[4], fmaf(rb3, a10[3], fmaf(rb2, a10[2], fmaf(rb1, a10[1], rb0 * a10[0]))));
        float rad11 = fmaf(rb4, a11[4], fmaf(rb3, a11[3], fmaf(rb2, a11[2], fmaf(rb1, a11[1], rb0 * a11[0]))));

        // Solid harmonics order (y, z, x)
        float y0 = Y1C * ey, y1 = Y1C * ez, y2 = Y1C * ex;

        float n0v = nodes0[s * NCH + c];
        const float* n1p = nodes1 + ((size_t)s * NCH + c) * 3;
        float n1x = n1p[0], n1y = n1p[1], n1z = n1p[2];

        if (valid) {
            // l_o = 0
            m0a = fmaf(W000f, n0v * rad00, m0a);
            float dot11 = fmaf(n1x, y0, fmaf(n1y, y1, n1z * y2));
            m0b = fmaf(W110f * rad11, dot11, m0b);
            // l_o = 1
            float t01 = W011 * n0v * rad01;
            m1a0 = fmaf(t01, y0, m1a0);
            m1a1 = fmaf(t01, y1, m1a1);
            m1a2 = fmaf(t01, y2, m1a2);
            float t10 = W101f * rad10;
            m1b0 = fmaf(t10, n1x, m1b0);
            m1b1 = fmaf(t10, n1y, m1b1);
            m1b2 = fmaf(t10, n1z, m1b2);
            float t11 = W111f * rad11;     // f11[m] = rad11 * y[m]; cross(n1, f11)
            m1c0 = fmaf(t11, n1y * y2 - n1z * y1, m1c0);
            m1c1 = fmaf(t11, n1z * y0 - n1x * y2, m1c1);
            m1c2 = fmaf(t11, n1x * y1 - n1y * y0, m1c2);
        }
    }

    // Combine the two half-warps.
    const unsigned FULL = 0xffffffffu;
    m0a  += __shfl_xor_sync(FULL, m0a, 16);
    m0b  += __shfl_xor_sync(FULL, m0b, 16);
    m1a0 += __shfl_xor_sync(FULL, m1a0, 16);
    m1a1 += __shfl_xor_sync(FULL, m1a1, 16);
    m1a2 += __shfl_xor_sync(FULL, m1a2, 16);
    m1b0 += __shfl_xor_sync(FULL, m1b0, 16);
    m1b1 += __shfl_xor_sync(FULL, m1b1, 16);
    m1b2 += __shfl_xor_sync(FULL, m1b2, 16);
    m1c0 += __shfl_xor_sync(FULL, m1c0, 16);
    m1c1 += __shfl_xor_sync(FULL, m1c1, 16);
    m1c2 += __shfl_xor_sync(FULL, m1c2, 16);

    if (half == 0) {
        out0[warp * 32 + c]      = m0a;
        out0[warp * 32 + 16 + c] = m0b;
        float* oa = out1 + ((size_t)warp * 48 + c) * 3;
        oa[0] = m1a0; oa[1] = m1a1; oa[2] = m1a2;
        float* ob = out1 + ((size_t)warp * 48 + 16 + c) * 3;
        ob[0] = m1b0; ob[1] = m1b1; ob[2] = m1b2;
        float* oc = out1 + ((size_t)warp * 48 + 32 + c) * 3;
        oc[0] = m1c0; oc[1] = m1c1; oc[2] = m1c2;
    }
}

extern "C" void kernel_launch(void* const* d_in, const int* in_sizes, int n_in,
                              void* d_out, int out_size) {
    const float* coords  = (const float*)d_in[0];
    const float* nodes0  = (const float*)d_in[1];
    const float* nodes1  = (const float*)d_in[2];
    const float* edges   = (const float*)d_in[3];
    const int*   senders = (const int*)d_in[4];
    const int*   recv    = (const int*)d_in[5];
    const float* c00 = (const float*)d_in[6];
    const float* c01 = (const float*)d_in[7];
    const float* c10 = (const float*)d_in[8];
    const float* c11 = (const float*)d_in[9];
    const float* w000 = (const float*)d_in[10];
    const float* w011 = (const float*)d_in[11];
    const float* w101 = (const float*)d_in[12];
    const float* w110 = (const float*)d_in[13];
    const float* w111 = (const float*)d_in[14];
    float* out = (float*)d_out;

    int N = in_sizes[0] / 3;
    int E = in_sizes[3] / 3;

    // coords passthrough
    cudaMemcpyAsync(out, coords, (size_t)3 * N * sizeof(float),
                    cudaMemcpyDeviceToDevice);
    float* out0 = out + (size_t)3 * N;
    float* out1 = out0 + (size_t)32 * N;

    k_zero<<<(N + 255) / 256, 256>>>(N);
    k_hist<<<(E + 255) / 256, 256>>>(recv, E);
    k_scan<<<1, 1024>>>(N);
    k_scatter<<<(E + 255) / 256, 256>>>(recv, E);
    k_main<<<(N * 32 + 255) / 256, 256>>>(nodes0, nodes1, edges, senders,
                                          c00, c01, c10, c11,
                                          w000, w011, w101, w110, w111,
                                          out0, out1, N);
}